// round 17
// baseline (speedup 1.0000x reference)
#include <cuda_runtime.h>
#include <cuda_fp16.h>
#include <math.h>
#include <stdint.h>

// Problem constants
#define BB 2
#define TT 2048
#define DD 2048
#define HH 32
#define KVH 8
#define HDIM 64
#define GG 4
#define NQKV 3072
#define MM (BB*TT)

// ---------------- scratch ----------
__device__ float  g_qkv[MM * NQKV];
__device__ __half g_x16[(size_t)MM * DD];
__device__ __half g_wqkvT16[(size_t)NQKV * DD];
__device__ __half g_woutT16[(size_t)DD * DD];
__device__ __half g_q16[(size_t)BB * HH * TT * HDIM];
__device__ __half g_k16[(size_t)BB * KVH * TT * HDIM];
__device__ __half g_v16[(size_t)BB * KVH * TT * HDIM];    // TRANSPOSED [b][kvh][d][t]
__device__ __half g_attn16[(size_t)MM * DD];

__device__ __forceinline__ float nan_clamp(float x) {
    if (isnan(x)) return 0.0f;
    if (isinf(x)) return x > 0.0f ? 10000.0f : -10000.0f;
    return x;
}

__device__ __forceinline__ void mma_f16(float& c0, float& c1, float& c2, float& c3,
                                        uint32_t a0, uint32_t a1, uint32_t a2, uint32_t a3,
                                        uint32_t b0, uint32_t b1) {
    asm volatile(
        "mma.sync.aligned.m16n8k16.row.col.f32.f16.f16.f32 "
        "{%0,%1,%2,%3}, {%4,%5,%6,%7}, {%8,%9}, {%0,%1,%2,%3};\n"
        : "+f"(c0), "+f"(c1), "+f"(c2), "+f"(c3)
        : "r"(a0), "r"(a1), "r"(a2), "r"(a3), "r"(b0), "r"(b1));
}

__device__ __forceinline__ void ldsm_x4(uint32_t& r0, uint32_t& r1, uint32_t& r2, uint32_t& r3,
                                        uint32_t saddr) {
    asm volatile("ldmatrix.sync.aligned.m8n8.x4.shared.b16 {%0,%1,%2,%3}, [%4];\n"
                 : "=r"(r0), "=r"(r1), "=r"(r2), "=r"(r3) : "r"(saddr) : "memory");
}

__device__ __forceinline__ void cp_async16(uint32_t smem_dst, const void* gmem_src) {
    asm volatile("cp.async.cg.shared.global [%0], [%1], 16;\n" :: "r"(smem_dst), "l"(gmem_src));
}

template<int N> __device__ __forceinline__ void cp_wait() {
    asm volatile("cp.async.wait_group %0;\n" :: "n"(N) : "memory");
}

// ---------------------------------------------------------------------------
// Prep kernels (unchanged)
// ---------------------------------------------------------------------------
__global__ void round_fp16_kernel(const float* __restrict__ in, __half* __restrict__ out, int n4)
{
    int stride = gridDim.x * blockDim.x;
    for (int i = blockIdx.x * blockDim.x + threadIdx.x; i < n4; i += stride) {
        float4 v = ((const float4*)in)[i];
        __half2 h0 = __floats2half2_rn(v.x, v.y);
        __half2 h1 = __floats2half2_rn(v.z, v.w);
        uint2 u;
        u.x = *(uint32_t*)&h0;
        u.y = *(uint32_t*)&h1;
        ((uint2*)out)[i] = u;
    }
}

__global__ void transpose_fp16_kernel(const float* __restrict__ in, __half* __restrict__ out,
                                      int K, int N)
{
    __shared__ float tile[32][33];
    int k0 = blockIdx.y * 32;
    int n0 = blockIdx.x * 32;
    int tx = threadIdx.x;
    int ty = threadIdx.y;
#pragma unroll
    for (int j = 0; j < 4; j++) {
        int kk = ty + j * 8;
        tile[kk][tx] = in[(size_t)(k0 + kk) * N + n0 + tx];
    }
    __syncthreads();
#pragma unroll
    for (int j = 0; j < 4; j++) {
        int nn = ty + j * 8;
        out[(size_t)(n0 + nn) * K + k0 + tx] = __float2half_rn(tile[tx][nn]);
    }
}

// ---------------------------------------------------------------------------
// FP16 GEMM: 256x128 CTA tile, 8 warps (4m x 2n), 64x64 per warp, BK=32,
// 3-stage cp.async ring.  As [256][40], Bs [128][40] halves.
// ---------------------------------------------------------------------------
#define TSH 40
#define STAGE_H ((256 + 128) * TSH)      // 15360 halves = 30720 B / stage

template <int EPI>
__global__ void __launch_bounds__(256, 1) mma_gemm_f16_kernel(
    const __half* __restrict__ A, const __half* __restrict__ Bt,
    float* __restrict__ C, const float* __restrict__ bias,
    int Md, int Nd, int Kd)
{
    extern __shared__ __half smh[];

    const int tid = threadIdx.x;
    const int m0 = blockIdx.y * 256;
    const int n0 = blockIdx.x * 128;

    const int w  = tid >> 5;           // 0..7
    const int l  = tid & 31;
    const int wm = (w >> 1) * 64;      // 0,64,128,192
    const int wn = (w & 1) * 64;       // 0,64
    const int g  = l >> 2;
    const int t4 = l & 3;

    const uint32_t smem_u32 = (uint32_t)__cvta_generic_to_shared(smh);
    const int row_a = (l & 7) + ((l >> 3) & 1) * 8;
    const int ka    = (l >> 4) * 8;
    const uint32_t a_lane = (uint32_t)((row_a * TSH + ka) * 2);
    const int row_b = (l & 7) + ((l >> 4) << 3);
    const int kb_   = ((l >> 3) & 1) * 8;
    const uint32_t b_lane = (uint32_t)((256 * TSH + row_b * TSH + kb_) * 2);

    float acc[4][8][4];
#pragma unroll
    for (int mt = 0; mt < 4; mt++)
#pragma unroll
        for (int nt = 0; nt < 8; nt++)
#pragma unroll
            for (int r = 0; r < 4; r++) acc[mt][nt][r] = 0.0f;

    const int nk = Kd >> 5;

    auto issue_stage = [&](int k0, int s) {
        uint32_t As_u = smem_u32 + (uint32_t)(s * STAGE_H * 2);
        uint32_t Bs_u = As_u + (uint32_t)(256 * TSH * 2);
        // A: 256 rows x 4 chunks = 1024
#pragma unroll
        for (int it = 0; it < 4; it++) {
            int idx = tid + it * 256;
            int m   = idx >> 2;
            int kq  = idx & 3;
            cp_async16(As_u + (uint32_t)((m * TSH + kq * 8) * 2),
                       &A[(size_t)(m0 + m) * Kd + k0 + kq * 8]);
        }
        // B: 128 rows x 4 chunks = 512
#pragma unroll
        for (int it = 0; it < 2; it++) {
            int idx = tid + it * 256;
            int n   = idx >> 2;
            int kq  = idx & 3;
            cp_async16(Bs_u + (uint32_t)((n * TSH + kq * 8) * 2),
                       &Bt[(size_t)(n0 + n) * Kd + k0 + kq * 8]);
        }
        asm volatile("cp.async.commit_group;\n");
    };

    issue_stage(0, 0);
    issue_stage(32, 1);

    for (int k = 0; k < nk; k++) {
        cp_wait<1>();
        __syncthreads();

        if (k + 2 < nk) issue_stage((k + 2) << 5, (k + 2) % 3);

        const uint32_t stage = smem_u32 + (uint32_t)((k % 3) * STAGE_H * 2);

#pragma unroll
        for (int kp = 0; kp < 2; kp++) {
            uint32_t bf[8][2];
#pragma unroll
            for (int j = 0; j < 4; j++)
                ldsm_x4(bf[2 * j][0], bf[2 * j][1], bf[2 * j + 1][0], bf[2 * j + 1][1],
                        stage + b_lane + (uint32_t)(((wn + j * 16) * TSH + kp * 16) * 2));
            uint32_t af[4][4];
#pragma unroll
            for (int mt = 0; mt < 4; mt++)
                ldsm_x4(af[mt][0], af[mt][1], af[mt][2], af[mt][3],
                        stage + a_lane + (uint32_t)(((wm + mt * 16) * TSH + kp * 16) * 2));
#pragma unroll
            for (int mt = 0; mt < 4; mt++)
#pragma unroll
                for (int nt = 0; nt < 8; nt++)
                    mma_f16(acc[mt][nt][0], acc[mt][nt][1], acc[mt][nt][2], acc[mt][nt][3],
                            af[mt][0], af[mt][1], af[mt][2], af[mt][3],
                            bf[nt][0], bf[nt][1]);
        }
    }

#pragma unroll
    for (int mt = 0; mt < 4; mt++) {
#pragma unroll
        for (int nt = 0; nt < 8; nt++) {
            int row = m0 + wm + mt * 16 + g;
            int col = n0 + wn + nt * 8 + 2 * t4;
            float2 v0 = make_float2(acc[mt][nt][0], acc[mt][nt][1]);
            float2 v1 = make_float2(acc[mt][nt][2], acc[mt][nt][3]);
            if (EPI) {
                v0.x = nan_clamp(v0.x + bias[col]);
                v0.y = nan_clamp(v0.y + bias[col + 1]);
                v1.x = nan_clamp(v1.x + bias[col]);
                v1.y = nan_clamp(v1.y + bias[col + 1]);
            }
            *(float2*)&C[(size_t)row * Nd + col]       = v0;
            *(float2*)&C[(size_t)(row + 8) * Nd + col] = v1;
        }
    }
}

// ---------------------------------------------------------------------------
// RoPE + split (unchanged)
// ---------------------------------------------------------------------------
__global__ void rope_split_kernel(
    const float* __restrict__ qkv,
    const float* __restrict__ rcos, const float* __restrict__ rsin,
    __half* __restrict__ q, __half* __restrict__ k, __half* __restrict__ v)
{
    int idx = blockIdx.x * blockDim.x + threadIdx.x;
    const int TOT = MM * (NQKV / 2);
    if (idx >= TOT) return;
    int m  = idx / (NQKV / 2);
    int c2 = idx - m * (NQKV / 2);
    int c  = c2 * 2;
    int b = m >> 11;
    int t = m & (TT - 1);

    float e = qkv[(size_t)m * NQKV + c];
    float o = qkv[(size_t)m * NQKV + c + 1];
    int d = c & (HDIM - 1);
    int i = d >> 1;

    if (c < HH * HDIM) {
        int h = c >> 6;
        float cs = rcos[t * (HDIM / 2) + i];
        float sn = rsin[t * (HDIM / 2) + i];
        size_t base = (((size_t)b * HH + h) * TT + t) * HDIM + d;
        *(__half2*)&q[base] = __floats2half2_rn(e * cs - o * sn, e * sn + o * cs);
    } else if (c < HH * HDIM + KVH * HDIM) {
        int kh = (c - HH * HDIM) >> 6;
        float cs = rcos[t * (HDIM / 2) + i];
        float sn = rsin[t * (HDIM / 2) + i];
        size_t base = (((size_t)b * KVH + kh) * TT + t) * HDIM + d;
        *(__half2*)&k[base] = __floats2half2_rn(e * cs - o * sn, e * sn + o * cs);
    } else {
        int kh = (c - HH * HDIM - KVH * HDIM) >> 6;
        size_t base = (((size_t)b * KVH + kh) * HDIM + d) * TT + t;
        v[base]      = __float2half_rn(e);
        v[base + TT] = __float2half_rn(o);
    }
}

// ---------------------------------------------------------------------------
// Causal flash attention: 256 threads / 8 warps, each warp owns 32 q-rows
// (mt=2 x 16-row A-tiles -> B-fragments reused twice: 320->192 B/MMA).
// 256-q-row CTA tile, 64-key tiles, double-buffered cp.async K/V.
// ---------------------------------------------------------------------------
#define FSH 72
#define FQ 256
#define QS_H   (FQ * FSH)
#define KV_H   (64 * FSH)
#define KS0_H  QS_H
#define VS0_H  (QS_H + 2 * KV_H)
#define PS0_H  (QS_H + 4 * KV_H)
#define FL_SMEM ((PS0_H + QS_H) * 2)   // 110592 B

__global__ void __launch_bounds__(256, 1) flash_kernel(
    const __half* __restrict__ Q, const __half* __restrict__ K,
    const __half* __restrict__ Vt, __half* __restrict__ Ob)
{
    extern __shared__ __half smh[];

    const int qt  = blockIdx.x;
    const int bh  = blockIdx.y;
    const int b   = bh / HH;
    const int h   = bh - b * HH;
    const int kvh = h / GG;
    const int tid = threadIdx.x;
    const int w   = tid >> 5;          // 0..7, owns rows w*32..w*32+31
    const int l   = tid & 31;
    const int g   = l >> 2;
    const int t4  = l & 3;

    const __half* qptr  = Q  + (((size_t)b * HH + h) * TT + (size_t)qt * FQ) * HDIM;
    const __half* kptr  = K  + (((size_t)b * KVH + kvh) * TT) * HDIM;
    const __half* vtptr = Vt + (((size_t)b * KVH + kvh) * HDIM) * TT;

    const uint32_t smem_u32 = (uint32_t)__cvta_generic_to_shared(smh);

    const int row_a = (l & 7) + ((l >> 3) & 1) * 8;
    const int ka    = (l >> 4) * 8;
    const uint32_t qa_base = smem_u32 + (uint32_t)(((w * 32 + row_a) * FSH + ka) * 2);
    const uint32_t pa_base = smem_u32 + (uint32_t)((PS0_H + (w * 32 + row_a) * FSH + ka) * 2);
    const int row_b = (l & 7) + ((l >> 4) << 3);
    const int kb_   = ((l >> 3) & 1) * 8;
    const uint32_t b_lane = (uint32_t)((row_b * FSH + kb_) * 2);

    // Q: 256 rows x 8 chunks = 2048 -> 8 iters
#pragma unroll
    for (int it = 0; it < 8; it++) {
        int idx = tid + it * 256;
        int row = idx >> 3;
        int dq  = idx & 7;
        cp_async16(smem_u32 + (uint32_t)((row * FSH + dq * 8) * 2),
                   &qptr[row * 64 + dq * 8]);
    }
    {
        // K/V tile 0: 512 chunks each -> 2 iters
#pragma unroll
        for (int it = 0; it < 2; it++) {
            int idx = tid + it * 256;
            int row = idx >> 3;
            int dq  = idx & 7;
            cp_async16(smem_u32 + (uint32_t)((KS0_H + row * FSH + dq * 8) * 2),
                       &kptr[(size_t)row * 64 + dq * 8]);
            cp_async16(smem_u32 + (uint32_t)((VS0_H + row * FSH + dq * 8) * 2),
                       &vtptr[(size_t)row * TT + dq * 8]);
        }
        asm volatile("cp.async.commit_group;\n");
    }

    // per-thread rows: mt in {0,1}: rows w*32 + mt*16 + g  and  +8
    float mx[2][2], li[2][2];
    float o[2][8][4];
#pragma unroll
    for (int mt = 0; mt < 2; mt++) {
        mx[mt][0] = mx[mt][1] = -1e30f;
        li[mt][0] = li[mt][1] = 0.0f;
#pragma unroll
        for (int nt = 0; nt < 8; nt++)
#pragma unroll
            for (int r = 0; r < 4; r++) o[mt][nt][r] = 0.0f;
    }

    const float scale = 0.125f;
    const int ktmax = 4 * qt + 3;

    for (int kt = 0; kt <= ktmax; kt++) {
        __syncthreads();

        if (kt < ktmax) {
            int nkt = kt + 1;
            uint32_t kb = smem_u32 + (uint32_t)((KS0_H + (nkt & 1) * KV_H) * 2);
            uint32_t vb = smem_u32 + (uint32_t)((VS0_H + (nkt & 1) * KV_H) * 2);
#pragma unroll
            for (int it = 0; it < 2; it++) {
                int idx = tid + it * 256;
                int row = idx >> 3;
                int dq  = idx & 7;
                cp_async16(kb + (uint32_t)((row * FSH + dq * 8) * 2),
                           &kptr[((size_t)nkt * 64 + row) * 64 + dq * 8]);
                cp_async16(vb + (uint32_t)((row * FSH + dq * 8) * 2),
                           &vtptr[(size_t)row * TT + nkt * 64 + dq * 8]);
            }
            asm volatile("cp.async.commit_group;\n");
            cp_wait<1>();
        } else {
            cp_wait<0>();
        }
        __syncthreads();

        if (kt * 64 > qt * FQ + w * 32 + 31) continue;

        const uint32_t kb_buf = smem_u32 + (uint32_t)((KS0_H + (kt & 1) * KV_H) * 2) + b_lane;
        const uint32_t vb_buf = smem_u32 + (uint32_t)((VS0_H + (kt & 1) * KV_H) * 2) + b_lane;

        // ---- S = Q K^T ----
        float s[2][8][4];
#pragma unroll
        for (int mt = 0; mt < 2; mt++)
#pragma unroll
            for (int nt = 0; nt < 8; nt++)
#pragma unroll
                for (int r = 0; r < 4; r++) s[mt][nt][r] = 0.0f;

#pragma unroll
        for (int kp = 0; kp < 4; kp++) {
            uint32_t bf[8][2];
#pragma unroll
            for (int j = 0; j < 4; j++)
                ldsm_x4(bf[2 * j][0], bf[2 * j][1], bf[2 * j + 1][0], bf[2 * j + 1][1],
                        kb_buf + (uint32_t)((j * 16 * FSH + kp * 16) * 2));
#pragma unroll
            for (int mt = 0; mt < 2; mt++) {
                uint32_t a0, a1, a2, a3;
                ldsm_x4(a0, a1, a2, a3, qa_base + (uint32_t)((mt * 16 * FSH + kp * 16) * 2));
#pragma unroll
                for (int nt = 0; nt < 8; nt++)
                    mma_f16(s[mt][nt][0], s[mt][nt][1], s[mt][nt][2], s[mt][nt][3],
                            a0, a1, a2, a3, bf[nt][0], bf[nt][1]);
            }
        }

        // ---- scale + causal mask ----
        if (kt >= 4 * qt) {
            const int kgb = kt * 64 + 2 * t4;
#pragma unroll
            for (int mt = 0; mt < 2; mt++) {
                int rA = qt * FQ + w * 32 + mt * 16 + g;
                int rB = rA + 8;
#pragma unroll
                for (int nt = 0; nt < 8; nt++) {
                    int kg = kgb + nt * 8;
                    s[mt][nt][0] = (kg     > rA) ? -1e30f : s[mt][nt][0] * scale;
                    s[mt][nt][1] = (kg + 1 > rA) ? -1e30f : s[mt][nt][1] * scale;
                    s[mt][nt][2] = (kg     > rB) ? -1e30f : s[mt][nt][2] * scale;
                    s[mt][nt][3] = (kg + 1 > rB) ? -1e30f : s[mt][nt][3] * scale;
                }
            }
        } else {
#pragma unroll
            for (int mt = 0; mt < 2; mt++)
#pragma unroll
                for (int nt = 0; nt < 8; nt++) {
                    s[mt][nt][0] *= scale; s[mt][nt][1] *= scale;
                    s[mt][nt][2] *= scale; s[mt][nt][3] *= scale;
                }
        }

        // ---- online softmax + P fp16 ----
        __half2 ph[2][8][2];
#pragma unroll
        for (int mt = 0; mt < 2; mt++) {
            float rm0 = -1e30f, rm1 = -1e30f;
#pragma unroll
            for (int nt = 0; nt < 8; nt++) {
                rm0 = fmaxf(rm0, fmaxf(s[mt][nt][0], s[mt][nt][1]));
                rm1 = fmaxf(rm1, fmaxf(s[mt][nt][2], s[mt][nt][3]));
            }
            rm0 = fmaxf(rm0, __shfl_xor_sync(0xffffffffu, rm0, 1));
            rm0 = fmaxf(rm0, __shfl_xor_sync(0xffffffffu, rm0, 2));
            rm1 = fmaxf(rm1, __shfl_xor_sync(0xffffffffu, rm1, 1));
            rm1 = fmaxf(rm1, __shfl_xor_sync(0xffffffffu, rm1, 2));

            float nm0 = fmaxf(mx[mt][0], rm0);
            float nm1 = fmaxf(mx[mt][1], rm1);
            float al0 = __expf(mx[mt][0] - nm0);
            float al1 = __expf(mx[mt][1] - nm1);
            mx[mt][0] = nm0; mx[mt][1] = nm1;

            float rs0 = 0.0f, rs1 = 0.0f;
#pragma unroll
            for (int nt = 0; nt < 8; nt++) {
                __half2 p01 = __floats2half2_rn(__expf(s[mt][nt][0] - nm0),
                                                __expf(s[mt][nt][1] - nm0));
                __half2 p23 = __floats2half2_rn(__expf(s[mt][nt][2] - nm1),
                                                __expf(s[mt][nt][3] - nm1));
                ph[mt][nt][0] = p01;
                ph[mt][nt][1] = p23;
                float2 f01 = __half22float2(p01);
                float2 f23 = __half22float2(p23);
                rs0 += f01.x + f01.y;
                rs1 += f23.x + f23.y;
            }
            rs0 += __shfl_xor_sync(0xffffffffu, rs0, 1);
            rs0 += __shfl_xor_sync(0xffffffffu, rs0, 2);
            rs1 += __shfl_xor_sync(0xffffffffu, rs1, 1);
            rs1 += __shfl_xor_sync(0xffffffffu, rs1, 2);

            li[mt][0] = li[mt][0] * al0 + rs0;
            li[mt][1] = li[mt][1] * al1 + rs1;
#pragma unroll
            for (int nt = 0; nt < 8; nt++) {
                o[mt][nt][0] *= al0; o[mt][nt][1] *= al0;
                o[mt][nt][2] *= al1; o[mt][nt][3] *= al1;
            }
        }

        // ---- store P (warp-private rows) ----
        __half* Ps = smh + PS0_H;
#pragma unroll
        for (int mt = 0; mt < 2; mt++)
#pragma unroll
            for (int nt = 0; nt < 8; nt++) {
                *(__half2*)&Ps[(w * 32 + mt * 16 + g)     * FSH + nt * 8 + 2 * t4] = ph[mt][nt][0];
                *(__half2*)&Ps[(w * 32 + mt * 16 + g + 8) * FSH + nt * 8 + 2 * t4] = ph[mt][nt][1];
            }
        __syncwarp();

        // ---- O += P V ----
#pragma unroll
        for (int kp = 0; kp < 4; kp++) {
            uint32_t bf[8][2];
#pragma unroll
            for (int j = 0; j < 4; j++)
                ldsm_x4(bf[2 * j][0], bf[2 * j][1], bf[2 * j + 1][0], bf[2 * j + 1][1],
                        vb_buf + (uint32_t)((j * 16 * FSH + kp * 16) * 2));
#pragma unroll
            for (int mt = 0; mt < 2; mt++) {
                uint32_t a0, a1, a2, a3;
                ldsm_x4(a0, a1, a2, a3, pa_base + (uint32_t)((mt * 16 * FSH + kp * 16) * 2));
#pragma unroll
                for (int nt = 0; nt < 8; nt++)
                    mma_f16(o[mt][nt][0], o[mt][nt][1], o[mt][nt][2], o[mt][nt][3],
                            a0, a1, a2, a3, bf[nt][0], bf[nt][1]);
            }
        }
    }

    // finalize + fp16 output
#pragma unroll
    for (int mt = 0; mt < 2; mt++) {
        float inv0 = 1.0f / li[mt][0];
        float inv1 = 1.0f / li[mt][1];
        size_t row0 = (size_t)b * TT + (size_t)qt * FQ + w * 32 + mt * 16 + g;
#pragma unroll
        for (int nt = 0; nt < 8; nt++) {
            int col = h * HDIM + nt * 8 + 2 * t4;
            *(__half2*)&Ob[row0 * DD + col] =
                __floats2half2_rn(o[mt][nt][0] * inv0, o[mt][nt][1] * inv0);
            *(__half2*)&Ob[(row0 + 8) * DD + col] =
                __floats2half2_rn(o[mt][nt][2] * inv1, o[mt][nt][3] * inv1);
        }
    }
}

// ---------------------------------------------------------------------------
extern "C" void kernel_launch(void* const* d_in, const int* in_sizes, int n_in,
                              void* d_out, int out_size)
{
    const float* x    = (const float*)d_in[0];
    const float* Wqkv = (const float*)d_in[1];
    const float* Wout = (const float*)d_in[2];
    const float* bout = (const float*)d_in[3];
    const float* rcos = (const float*)d_in[4];
    const float* rsin = (const float*)d_in[5];
    float* out = (float*)d_out;

    float* qkv;
    __half *x16, *wqkvT16, *woutT16, *q16, *k16, *v16, *attn16;
    cudaGetSymbolAddress((void**)&qkv,     g_qkv);
    cudaGetSymbolAddress((void**)&x16,     g_x16);
    cudaGetSymbolAddress((void**)&wqkvT16, g_wqkvT16);
    cudaGetSymbolAddress((void**)&woutT16, g_woutT16);
    cudaGetSymbolAddress((void**)&q16,     g_q16);
    cudaGetSymbolAddress((void**)&k16,     g_k16);
    cudaGetSymbolAddress((void**)&v16,     g_v16);
    cudaGetSymbolAddress((void**)&attn16,  g_attn16);

    // 0. Prep
    round_fp16_kernel<<<1184, 256>>>(x, x16, (MM * DD) / 4);
    transpose_fp16_kernel<<<dim3(NQKV / 32, DD / 32), dim3(32, 8)>>>(Wqkv, wqkvT16, DD, NQKV);
    transpose_fp16_kernel<<<dim3(DD / 32, DD / 32),   dim3(32, 8)>>>(Wout, woutT16, DD, DD);

    const int gemm_smem = 3 * STAGE_H * 2;   // 92160 B

    // 1. QKV projection
    {
        cudaFuncSetAttribute(mma_gemm_f16_kernel<0>, cudaFuncAttributeMaxDynamicSharedMemorySize, gemm_smem);
        dim3 grid(NQKV / 128, MM / 256);      // 24 x 16
        mma_gemm_f16_kernel<0><<<grid, 256, gemm_smem>>>(x16, wqkvT16, qkv, nullptr, MM, NQKV, DD);
    }

    // 2. RoPE + split
    {
        int tot = MM * (NQKV / 2);
        rope_split_kernel<<<(tot + 255) / 256, 256>>>(qkv, rcos, rsin, q16, k16, v16);
    }

    // 3. Causal flash attention
    {
        cudaFuncSetAttribute(flash_kernel, cudaFuncAttributeMaxDynamicSharedMemorySize, FL_SMEM);
        dim3 grid(TT / FQ, BB * HH);          // 8 x 64
        flash_kernel<<<grid, 256, FL_SMEM>>>(q16, k16, v16, attn16);
    }

    // 4. Out projection + bias + nan_to_num
    {
        cudaFuncSetAttribute(mma_gemm_f16_kernel<1>, cudaFuncAttributeMaxDynamicSharedMemorySize, gemm_smem);
        dim3 grid(DD / 128, MM / 256);        // 16 x 16
        mma_gemm_f16_kernel<1><<<grid, 256, gemm_smem>>>(attn16, woutT16, out, bout, MM, DD, DD);
    }
}